// round 1
// baseline (speedup 1.0000x reference)
#include <cuda_runtime.h>
#include <cuda_bf16.h>
#include <math.h>

// Problem constants (fixed shapes)
#define TT 512   // timesteps
#define BB 64    // batch
#define HH 512   // hidden
#define II 128   // input
#define OO 64    // output
#define CL 8     // CTAs per cluster
#define NB 4     // batches per cluster
#define JS 64    // hidden rows per CTA (HH / CL)
#define WSS 516  // padded SMEM row stride for W_rec slice (conflict-free)

#define ALPHA 0.1f

// Scratch (allowed: __device__ globals, no runtime allocation)
__device__ float g_xproj[(size_t)BB * TT * HH];  // 64 MB
__device__ float g_h[2][BB * HH];                // double-buffered hidden state

// ---------------------------------------------------------------------------
// Phase 1: x_proj[b,t,h] = sum_i inputs[b,t,i] * W_in[h,i]
// Tiled 64x64 GEMM, K=128 in 2 chunks, 16x16 threads, 4x4 microtile.
// ---------------------------------------------------------------------------
__global__ void __launch_bounds__(256) xproj_kernel(const float* __restrict__ A,
                                                    const float* __restrict__ Win) {
    __shared__ float As[64 * 65];
    __shared__ float Bs[64 * 65];
    int mb = blockIdx.x;   // 0..511  (row tile over B*T = 32768)
    int hb = blockIdx.y;   // 0..7    (col tile over H = 512)
    int tid = threadIdx.x;
    int tx = tid & 15, ty = tid >> 4;

    float acc[4][4];
#pragma unroll
    for (int i = 0; i < 4; ++i)
#pragma unroll
        for (int j = 0; j < 4; ++j) acc[i][j] = 0.f;

    for (int kc = 0; kc < 2; ++kc) {
#pragma unroll
        for (int i = 0; i < 4; ++i) {
            int f = tid + i * 256;            // 0..1023
            int c4 = f & 15, r = f >> 4;      // 16 float4 per row, 64 rows
            float4 va = *(const float4*)(A + (size_t)(mb * 64 + r) * II + kc * 64 + c4 * 4);
            As[r * 65 + c4 * 4 + 0] = va.x;
            As[r * 65 + c4 * 4 + 1] = va.y;
            As[r * 65 + c4 * 4 + 2] = va.z;
            As[r * 65 + c4 * 4 + 3] = va.w;
            float4 vb = *(const float4*)(Win + (size_t)(hb * 64 + r) * II + kc * 64 + c4 * 4);
            Bs[r * 65 + c4 * 4 + 0] = vb.x;
            Bs[r * 65 + c4 * 4 + 1] = vb.y;
            Bs[r * 65 + c4 * 4 + 2] = vb.z;
            Bs[r * 65 + c4 * 4 + 3] = vb.w;
        }
        __syncthreads();
#pragma unroll 16
        for (int k = 0; k < 64; ++k) {
            float a0 = As[(ty * 4 + 0) * 65 + k];
            float a1 = As[(ty * 4 + 1) * 65 + k];
            float a2 = As[(ty * 4 + 2) * 65 + k];
            float a3 = As[(ty * 4 + 3) * 65 + k];
            float b0 = Bs[(tx * 4 + 0) * 65 + k];
            float b1 = Bs[(tx * 4 + 1) * 65 + k];
            float b2 = Bs[(tx * 4 + 2) * 65 + k];
            float b3 = Bs[(tx * 4 + 3) * 65 + k];
            acc[0][0] += a0 * b0; acc[0][1] += a0 * b1; acc[0][2] += a0 * b2; acc[0][3] += a0 * b3;
            acc[1][0] += a1 * b0; acc[1][1] += a1 * b1; acc[1][2] += a1 * b2; acc[1][3] += a1 * b3;
            acc[2][0] += a2 * b0; acc[2][1] += a2 * b1; acc[2][2] += a2 * b2; acc[2][3] += a2 * b3;
            acc[3][0] += a3 * b0; acc[3][1] += a3 * b1; acc[3][2] += a3 * b2; acc[3][3] += a3 * b3;
        }
        __syncthreads();
    }
#pragma unroll
    for (int i = 0; i < 4; ++i) {
        float4 v = make_float4(acc[i][0], acc[i][1], acc[i][2], acc[i][3]);
        *(float4*)(g_xproj + (size_t)(mb * 64 + ty * 4 + i) * HH + hb * 64 + tx * 4) = v;
    }
}

// ---------------------------------------------------------------------------
// Phase 2: per-cluster recurrent scan.
// 16 clusters x 8 CTAs. Cluster c owns batches [c*4, c*4+4).
// CTA rank r owns W_rec rows [r*64, r*64+64) in SMEM (stride 516, conflict-free)
// and W_out rows [r*8, r*8+8) in registers.
// Each step: GEMV slice (FFMA-bound), exchange h via L2 + barrier.cluster,
// restage full h into SMEM, compute output slice.
// ---------------------------------------------------------------------------
extern __shared__ float smem2[];

__global__ void __launch_bounds__(256, 1) rnn_scan_kernel(
    const float* __restrict__ hidden0,
    const float* __restrict__ Wrec,
    const float* __restrict__ bvec,
    const float* __restrict__ Wout,
    const float* __restrict__ bout,
    float* __restrict__ out,      // [B,T,O]
    float* __restrict__ hfinal)   // [B,H]
{
    float* Ws  = smem2;                        // JS * WSS
    float* hs  = Ws + JS * WSS;                // NB * HH
    float* red = hs + NB * HH;                 // 8 * 256
    float* bsl = red + 8 * 256;                // JS

    int tid = threadIdx.x;
    int lane = tid & 31, warp = tid >> 5;
    unsigned rank;
    asm("mov.u32 %0, %%cluster_ctarank;" : "=r"(rank));
    int cid = blockIdx.x / CL;
    int cbase = cid * NB;          // first batch of this cluster
    int jbase = (int)rank * JS;    // first hidden row of this CTA

    // ---- load W_rec slice into SMEM (padded rows) ----
    for (int f = tid; f < JS * HH / 4; f += 256) {
        int j = f >> 7;            // 128 float4 per 512-wide row
        int c4 = f & 127;
        float4 v = *(const float4*)(Wrec + (size_t)(jbase + j) * HH + c4 * 4);
        *(float4*)&Ws[j * WSS + c4 * 4] = v;
    }
    if (tid < JS) bsl[tid] = bvec[jbase + tid];

    // ---- preload W_out slice into registers ----
    // warp -> (batch wb, output-group og of 4)
    int wb = warp >> 1;
    int og = (warp & 1) * 4;
    float4 wo[4][4];
#pragma unroll
    for (int oi = 0; oi < 4; ++oi)
#pragma unroll
        for (int m = 0; m < 4; ++m)
            wo[oi][m] = *(const float4*)(Wout + (size_t)(rank * 8 + og + oi) * HH + lane * 4 + m * 128);
    float4 bo4 = *(const float4*)(bout + rank * 8 + og);

    // ---- stage initial hidden into SMEM ----
    {
        const float4* src = (const float4*)(hidden0 + (size_t)cbase * HH);
        ((float4*)hs)[tid]       = src[tid];
        ((float4*)hs)[tid + 256] = src[tid + 256];
    }
    __syncthreads();

    int rb = tid >> 6;             // reduction batch (0..3)
    int jl = tid & 63;             // reduction local hidden row
    int ridx = ((jl >> 5) * 4 + rb) * 32 + (jl & 31);
    int kb = warp * 64;            // this warp's k range

    for (int t = 0; t < TT; ++t) {
        // prefetch input projection for this thread's (b, j)
        float xp = __ldg(&g_xproj[((size_t)(cbase + rb) * TT + t) * HH + jbase + jl]);

        // ---- recurrent GEMV slice: acc[r][b] partial over this warp's k ----
        float a00 = 0.f, a01 = 0.f, a02 = 0.f, a03 = 0.f;
        float a10 = 0.f, a11 = 0.f, a12 = 0.f, a13 = 0.f;
#pragma unroll
        for (int m = 0; m < 16; ++m) {
            int k = kb + m * 4;
            float4 h0 = *(const float4*)&hs[0 * HH + k];
            float4 h1 = *(const float4*)&hs[1 * HH + k];
            float4 h2 = *(const float4*)&hs[2 * HH + k];
            float4 h3 = *(const float4*)&hs[3 * HH + k];
            float4 w0 = *(const float4*)&Ws[lane * WSS + k];
            float4 w1 = *(const float4*)&Ws[(lane + 32) * WSS + k];
            a00 += w0.x * h0.x + w0.y * h0.y + w0.z * h0.z + w0.w * h0.w;
            a01 += w0.x * h1.x + w0.y * h1.y + w0.z * h1.z + w0.w * h1.w;
            a02 += w0.x * h2.x + w0.y * h2.y + w0.z * h2.z + w0.w * h2.w;
            a03 += w0.x * h3.x + w0.y * h3.y + w0.z * h3.z + w0.w * h3.w;
            a10 += w1.x * h0.x + w1.y * h0.y + w1.z * h0.z + w1.w * h0.w;
            a11 += w1.x * h1.x + w1.y * h1.y + w1.z * h1.z + w1.w * h1.w;
            a12 += w1.x * h2.x + w1.y * h2.y + w1.z * h2.z + w1.w * h2.w;
            a13 += w1.x * h3.x + w1.y * h3.y + w1.z * h3.z + w1.w * h3.w;
        }
        // partials -> SMEM (conflict-free both directions)
        red[warp * 256 + (0 * 4 + 0) * 32 + lane] = a00;
        red[warp * 256 + (0 * 4 + 1) * 32 + lane] = a01;
        red[warp * 256 + (0 * 4 + 2) * 32 + lane] = a02;
        red[warp * 256 + (0 * 4 + 3) * 32 + lane] = a03;
        red[warp * 256 + (1 * 4 + 0) * 32 + lane] = a10;
        red[warp * 256 + (1 * 4 + 1) * 32 + lane] = a11;
        red[warp * 256 + (1 * 4 + 2) * 32 + lane] = a12;
        red[warp * 256 + (1 * 4 + 3) * 32 + lane] = a13;
        __syncthreads();

        float s = 0.f;
#pragma unroll
        for (int w = 0; w < 8; ++w) s += red[w * 256 + ridx];

        float pre = s + bsl[jl] + xp;
        float hp = hs[rb * HH + jbase + jl];
        float hn = (1.0f - ALPHA) * hp + ALPHA * tanhf(pre);

        int q = t & 1;
        g_h[q][(cbase + rb) * HH + jbase + jl] = hn;
        if (t == TT - 1) hfinal[(cbase + rb) * HH + jbase + jl] = hn;

        // cluster barrier: release h writes, acquire peers' writes (flushes L1)
        asm volatile("barrier.cluster.arrive.aligned;" ::: "memory");
        asm volatile("barrier.cluster.wait.aligned;" ::: "memory");

        // ---- restage full h_{t+1} for this cluster's 4 batches ----
        {
            const float4* src = (const float4*)(&g_h[q][cbase * HH]);
            float4 v0 = __ldcg(src + tid);
            float4 v1 = __ldcg(src + tid + 256);
            ((float4*)hs)[tid]       = v0;
            ((float4*)hs)[tid + 256] = v1;
        }
        __syncthreads();

        // ---- output slice: out[wb][t][rank*8+og .. +3] from full h_new ----
        float o0 = 0.f, o1 = 0.f, o2 = 0.f, o3 = 0.f;
#pragma unroll
        for (int m = 0; m < 4; ++m) {
            float4 hv = *(const float4*)&hs[wb * HH + lane * 4 + m * 128];
            o0 += wo[0][m].x * hv.x + wo[0][m].y * hv.y + wo[0][m].z * hv.z + wo[0][m].w * hv.w;
            o1 += wo[1][m].x * hv.x + wo[1][m].y * hv.y + wo[1][m].z * hv.z + wo[1][m].w * hv.w;
            o2 += wo[2][m].x * hv.x + wo[2][m].y * hv.y + wo[2][m].z * hv.z + wo[2][m].w * hv.w;
            o3 += wo[3][m].x * hv.x + wo[3][m].y * hv.y + wo[3][m].z * hv.z + wo[3][m].w * hv.w;
        }
#pragma unroll
        for (int off = 16; off; off >>= 1) {
            o0 += __shfl_xor_sync(0xffffffffu, o0, off);
            o1 += __shfl_xor_sync(0xffffffffu, o1, off);
            o2 += __shfl_xor_sync(0xffffffffu, o2, off);
            o3 += __shfl_xor_sync(0xffffffffu, o3, off);
        }
        if (lane == 0) {
            float4 ov = make_float4(o0 + bo4.x, o1 + bo4.y, o2 + bo4.z, o3 + bo4.w);
            *(float4*)&out[((size_t)(cbase + wb) * TT + t) * OO + rank * 8 + og] = ov;
        }
        // no extra barrier: next step's red writes / hs writes are separated
        // from this step's reads by the next cluster.sync (CTA-wide barrier).
    }
}

// ---------------------------------------------------------------------------
extern "C" void kernel_launch(void* const* d_in, const int* in_sizes, int n_in,
                              void* d_out, int out_size) {
    const float* inputs = (const float*)d_in[0];   // [B,T,I]
    const float* hidden = (const float*)d_in[1];   // [B,H]
    const float* W_in   = (const float*)d_in[2];   // [H,I]
    const float* W_rec  = (const float*)d_in[3];   // [H,H]
    const float* b      = (const float*)d_in[4];   // [H]
    const float* W_out  = (const float*)d_in[5];   // [O,H]
    const float* b_out  = (const float*)d_in[6];   // [O]

    float* out    = (float*)d_out;                         // [B,T,O]
    float* hfinal = out + (size_t)BB * TT * OO;            // [B,H]

    // Phase 1: input projection
    xproj_kernel<<<dim3(512, 8), 256>>>(inputs, W_in);

    // Phase 2: clustered recurrent scan
    const size_t smem_bytes = (size_t)(JS * WSS + NB * HH + 8 * 256 + JS) * sizeof(float);
    cudaFuncSetAttribute(rnn_scan_kernel, cudaFuncAttributeMaxDynamicSharedMemorySize,
                         (int)smem_bytes);

    cudaLaunchConfig_t cfg = {};
    cfg.gridDim = dim3((BB / NB) * CL);   // 16 clusters * 8 CTAs = 128 blocks
    cfg.blockDim = dim3(256);
    cfg.dynamicSmemBytes = smem_bytes;
    cudaLaunchAttribute attrs[1];
    attrs[0].id = cudaLaunchAttributeClusterDimension;
    attrs[0].val.clusterDim.x = CL;
    attrs[0].val.clusterDim.y = 1;
    attrs[0].val.clusterDim.z = 1;
    cfg.attrs = attrs;
    cfg.numAttrs = 1;

    cudaLaunchKernelEx(&cfg, rnn_scan_kernel, hidden, W_rec, b, W_out, b_out, out, hfinal);
}

// round 3
// speedup vs baseline: 1.5011x; 1.5011x over previous
#include <cuda_runtime.h>
#include <cuda_bf16.h>
#include <math.h>

// Problem constants (fixed shapes)
#define TT 512   // timesteps
#define BB 64    // batch
#define HH 512   // hidden
#define II 128   // input
#define OO 64    // output
#define CL 8     // CTAs per cluster
#define NB 4     // batches per cluster
#define JS 64    // hidden rows per CTA (HH / CL)
#define WSS 516  // padded SMEM row stride (516*4B, 16B aligned; conflict-free LDS.128)
#define ALPHA 0.1f

// Scratch (allowed: __device__ global)
__device__ float g_xproj[(size_t)BB * TT * HH];  // 64 MB

// ---------------- PTX helpers ----------------
__device__ __forceinline__ void fma2(unsigned long long& d,
                                     unsigned long long a,
                                     unsigned long long b) {
    asm("fma.rn.f32x2 %0, %1, %2, %0;" : "+l"(d) : "l"(a), "l"(b));
}
__device__ __forceinline__ float hadd2(unsigned long long v) {
    unsigned lo, hi;
    asm("mov.b64 {%0,%1}, %2;" : "=r"(lo), "=r"(hi) : "l"(v));
    return __uint_as_float(lo) + __uint_as_float(hi);
}
__device__ __forceinline__ unsigned smem_u32(const void* p) {
    unsigned a;
    asm("{ .reg .u64 t; cvta.to.shared.u64 t, %1; cvt.u32.u64 %0, t; }"
        : "=r"(a) : "l"(p));
    return a;
}
__device__ __forceinline__ unsigned mapa_u32(unsigned addr, unsigned rank) {
    unsigned r;
    asm("mapa.shared::cluster.u32 %0, %1, %2;" : "=r"(r) : "r"(addr), "r"(rank));
    return r;
}
__device__ __forceinline__ void st_cluster_f32(unsigned addr, float v) {
    asm volatile("st.shared::cluster.f32 [%0], %1;" :: "r"(addr), "f"(v) : "memory");
}
__device__ __forceinline__ float fast_tanh(float x) {
    // 1 - 2/(1+exp(2x)); exact limits, ~1e-7 rel err via MUFU.EX2
    float e = __expf(2.0f * x);
    return 1.0f - __fdividef(2.0f, e + 1.0f);
}

// ---------------------------------------------------------------------------
// Phase 1: x_proj[b,t,h] = sum_i inputs[b,t,i] * W_in[h,i]
// ---------------------------------------------------------------------------
__global__ void __launch_bounds__(256) xproj_kernel(const float* __restrict__ A,
                                                    const float* __restrict__ Win) {
    __shared__ float As[64 * 65];
    __shared__ float Bs[64 * 65];
    int mb = blockIdx.x;
    int hb = blockIdx.y;
    int tid = threadIdx.x;
    int tx = tid & 15, ty = tid >> 4;

    float acc[4][4];
#pragma unroll
    for (int i = 0; i < 4; ++i)
#pragma unroll
        for (int j = 0; j < 4; ++j) acc[i][j] = 0.f;

    for (int kc = 0; kc < 2; ++kc) {
#pragma unroll
        for (int i = 0; i < 4; ++i) {
            int f = tid + i * 256;
            int c4 = f & 15, r = f >> 4;
            float4 va = *(const float4*)(A + (size_t)(mb * 64 + r) * II + kc * 64 + c4 * 4);
            As[r * 65 + c4 * 4 + 0] = va.x;
            As[r * 65 + c4 * 4 + 1] = va.y;
            As[r * 65 + c4 * 4 + 2] = va.z;
            As[r * 65 + c4 * 4 + 3] = va.w;
            float4 vb = *(const float4*)(Win + (size_t)(hb * 64 + r) * II + kc * 64 + c4 * 4);
            Bs[r * 65 + c4 * 4 + 0] = vb.x;
            Bs[r * 65 + c4 * 4 + 1] = vb.y;
            Bs[r * 65 + c4 * 4 + 2] = vb.z;
            Bs[r * 65 + c4 * 4 + 3] = vb.w;
        }
        __syncthreads();
#pragma unroll 16
        for (int k = 0; k < 64; ++k) {
            float a0 = As[(ty * 4 + 0) * 65 + k];
            float a1 = As[(ty * 4 + 1) * 65 + k];
            float a2 = As[(ty * 4 + 2) * 65 + k];
            float a3 = As[(ty * 4 + 3) * 65 + k];
            float b0 = Bs[(tx * 4 + 0) * 65 + k];
            float b1 = Bs[(tx * 4 + 1) * 65 + k];
            float b2 = Bs[(tx * 4 + 2) * 65 + k];
            float b3 = Bs[(tx * 4 + 3) * 65 + k];
            acc[0][0] += a0 * b0; acc[0][1] += a0 * b1; acc[0][2] += a0 * b2; acc[0][3] += a0 * b3;
            acc[1][0] += a1 * b0; acc[1][1] += a1 * b1; acc[1][2] += a1 * b2; acc[1][3] += a1 * b3;
            acc[2][0] += a2 * b0; acc[2][1] += a2 * b1; acc[2][2] += a2 * b2; acc[2][3] += a2 * b3;
            acc[3][0] += a3 * b0; acc[3][1] += a3 * b1; acc[3][2] += a3 * b2; acc[3][3] += a3 * b3;
        }
        __syncthreads();
    }
#pragma unroll
    for (int i = 0; i < 4; ++i) {
        float4 v = make_float4(acc[i][0], acc[i][1], acc[i][2], acc[i][3]);
        *(float4*)(g_xproj + (size_t)(mb * 64 + ty * 4 + i) * HH + hb * 64 + tx * 4) = v;
    }
}

// ---------------------------------------------------------------------------
// Phase 2: clustered recurrent scan. DSMEM push h-exchange (double-buffered),
// packed f32x2 FMA GEMV, fast tanh.
// ---------------------------------------------------------------------------
extern __shared__ float smem2[];

__global__ void __launch_bounds__(256, 1) rnn_scan_kernel(
    const float* __restrict__ hidden0,
    const float* __restrict__ Wrec,
    const float* __restrict__ bvec,
    const float* __restrict__ Wout,
    const float* __restrict__ bout,
    float* __restrict__ out,      // [B,T,O]
    float* __restrict__ hfinal)   // [B,H]
{
    float* Ws  = smem2;                        // JS * WSS
    float* hsA = Ws + JS * WSS;                // NB * HH
    float* hsB = hsA + NB * HH;                // NB * HH
    float* red = hsB + NB * HH;                // 8 * 256
    float* WoS = red + 8 * 256;                // 8 * HH
    float* bsl = WoS + 8 * HH;                 // JS

    int tid = threadIdx.x;
    int lane = tid & 31, warp = tid >> 5;
    unsigned rank;
    asm("mov.u32 %0, %%cluster_ctarank;" : "=r"(rank));
    int cid = blockIdx.x / CL;
    int cbase = cid * NB;
    int jbase = (int)rank * JS;

    // ---- load W_rec slice into SMEM ----
    for (int f = tid; f < JS * HH / 4; f += 256) {
        int j = f >> 7;
        int c4 = f & 127;
        float4 v = *(const float4*)(Wrec + (size_t)(jbase + j) * HH + c4 * 4);
        *(float4*)&Ws[j * WSS + c4 * 4] = v;
    }
    if (tid < JS) bsl[tid] = bvec[jbase + tid];

    // ---- W_out slice (8 rows) into SMEM ----
    for (int f = tid; f < 8 * HH / 4; f += 256) {
        int r = f >> 7, c4 = f & 127;
        *(float4*)&WoS[r * HH + c4 * 4] =
            *(const float4*)(Wout + (size_t)(rank * 8 + r) * HH + c4 * 4);
    }

    int wb = warp >> 1;
    int og = (warp & 1) * 4;
    float4 bo4 = *(const float4*)(bout + rank * 8 + og);

    // ---- stage initial hidden into hsA ----
    {
        const float4* src = (const float4*)(hidden0 + (size_t)cbase * HH);
        ((float4*)hsA)[tid]       = src[tid];
        ((float4*)hsA)[tid + 256] = src[tid + 256];
    }
    __syncthreads();

    int rb = tid >> 6;
    int jl = tid & 63;
    int ridx = ((jl >> 5) * 4 + rb) * 32 + (jl & 31);
    int kb = warp * 64;

    // precompute DSMEM scatter addresses
    unsigned myoff = (unsigned)((rb * HH + jbase + jl) * 4);
    unsigned hsA_u = smem_u32(hsA) + myoff;
    unsigned hsB_u = smem_u32(hsB) + myoff;
    unsigned dstA[CL], dstB[CL];
#pragma unroll
    for (int r = 0; r < CL; ++r) {
        dstA[r] = mapa_u32(hsA_u, (unsigned)r);
        dstB[r] = mapa_u32(hsB_u, (unsigned)r);
    }

    // cur = buffer holding h_t, nxtDst = scatter targets for h_{t+1}
    const float* cur = hsA;
    const float* nxt = hsB;
    const unsigned* curDst = dstB;
    const unsigned* nxtDst = dstA;

    for (int t = 0; t < TT; ++t) {
        float xp = __ldg(&g_xproj[((size_t)(cbase + rb) * TT + t) * HH + jbase + jl]);

        // ---- recurrent GEMV slice (packed f32x2) ----
        unsigned long long a00 = 0, a01 = 0, a02 = 0, a03 = 0;
        unsigned long long a10 = 0, a11 = 0, a12 = 0, a13 = 0;
#pragma unroll
        for (int m = 0; m < 16; ++m) {
            int k = kb + m * 4;
            ulonglong2 h0 = *(const ulonglong2*)&cur[0 * HH + k];
            ulonglong2 h1 = *(const ulonglong2*)&cur[1 * HH + k];
            ulonglong2 h2 = *(const ulonglong2*)&cur[2 * HH + k];
            ulonglong2 h3 = *(const ulonglong2*)&cur[3 * HH + k];
            ulonglong2 w0 = *(const ulonglong2*)&Ws[lane * WSS + k];
            ulonglong2 w1 = *(const ulonglong2*)&Ws[(lane + 32) * WSS + k];
            fma2(a00, w0.x, h0.x); fma2(a00, w0.y, h0.y);
            fma2(a01, w0.x, h1.x); fma2(a01, w0.y, h1.y);
            fma2(a02, w0.x, h2.x); fma2(a02, w0.y, h2.y);
            fma2(a03, w0.x, h3.x); fma2(a03, w0.y, h3.y);
            fma2(a10, w1.x, h0.x); fma2(a10, w1.y, h0.y);
            fma2(a11, w1.x, h1.x); fma2(a11, w1.y, h1.y);
            fma2(a12, w1.x, h2.x); fma2(a12, w1.y, h2.y);
            fma2(a13, w1.x, h3.x); fma2(a13, w1.y, h3.y);
        }
        red[warp * 256 + 0 * 32 + lane] = hadd2(a00);
        red[warp * 256 + 1 * 32 + lane] = hadd2(a01);
        red[warp * 256 + 2 * 32 + lane] = hadd2(a02);
        red[warp * 256 + 3 * 32 + lane] = hadd2(a03);
        red[warp * 256 + 4 * 32 + lane] = hadd2(a10);
        red[warp * 256 + 5 * 32 + lane] = hadd2(a11);
        red[warp * 256 + 6 * 32 + lane] = hadd2(a12);
        red[warp * 256 + 7 * 32 + lane] = hadd2(a13);
        __syncthreads();

        float s = 0.f;
#pragma unroll
        for (int w = 0; w < 8; ++w) s += red[w * 256 + ridx];

        float pre = s + bsl[jl] + xp;
        float hp = cur[rb * HH + jbase + jl];
        float hn = (1.0f - ALPHA) * hp + ALPHA * fast_tanh(pre);

        if (t == TT - 1) hfinal[(cbase + rb) * HH + jbase + jl] = hn;

        // ---- scatter hn into all 8 CTAs' next-buffer (DSMEM push) ----
#pragma unroll
        for (int r = 0; r < CL; ++r) st_cluster_f32(curDst[r], hn);

        // cluster barrier (release our DSMEM stores, acquire peers')
        asm volatile("barrier.cluster.arrive.aligned;" ::: "memory");
        asm volatile("barrier.cluster.wait.aligned;" ::: "memory");

        // ---- output slice from full h_{t+1} (= nxt buffer) ----
        unsigned long long o0 = 0, o1 = 0, o2 = 0, o3 = 0;
#pragma unroll
        for (int m = 0; m < 4; ++m) {
            ulonglong2 hv = *(const ulonglong2*)&nxt[wb * HH + lane * 4 + m * 128];
            ulonglong2 w0 = *(const ulonglong2*)&WoS[(og + 0) * HH + lane * 4 + m * 128];
            ulonglong2 w1 = *(const ulonglong2*)&WoS[(og + 1) * HH + lane * 4 + m * 128];
            ulonglong2 w2 = *(const ulonglong2*)&WoS[(og + 2) * HH + lane * 4 + m * 128];
            ulonglong2 w3 = *(const ulonglong2*)&WoS[(og + 3) * HH + lane * 4 + m * 128];
            fma2(o0, w0.x, hv.x); fma2(o0, w0.y, hv.y);
            fma2(o1, w1.x, hv.x); fma2(o1, w1.y, hv.y);
            fma2(o2, w2.x, hv.x); fma2(o2, w2.y, hv.y);
            fma2(o3, w3.x, hv.x); fma2(o3, w3.y, hv.y);
        }
        float f0 = hadd2(o0), f1 = hadd2(o1), f2 = hadd2(o2), f3 = hadd2(o3);
#pragma unroll
        for (int off = 16; off; off >>= 1) {
            f0 += __shfl_xor_sync(0xffffffffu, f0, off);
            f1 += __shfl_xor_sync(0xffffffffu, f1, off);
            f2 += __shfl_xor_sync(0xffffffffu, f2, off);
            f3 += __shfl_xor_sync(0xffffffffu, f3, off);
        }
        if (lane == 0) {
            float4 ov = make_float4(f0 + bo4.x, f1 + bo4.y, f2 + bo4.z, f3 + bo4.w);
            *(float4*)&out[((size_t)(cbase + wb) * TT + t) * OO + rank * 8 + og] = ov;
        }

        // swap buffers
        const float* tf = cur; cur = nxt; nxt = tf;
        const unsigned* td = curDst; curDst = nxtDst; nxtDst = td;
    }
}

// ---------------------------------------------------------------------------
extern "C" void kernel_launch(void* const* d_in, const int* in_sizes, int n_in,
                              void* d_out, int out_size) {
    const float* inputs = (const float*)d_in[0];   // [B,T,I]
    const float* hidden = (const float*)d_in[1];   // [B,H]
    const float* W_in   = (const float*)d_in[2];   // [H,I]
    const float* W_rec  = (const float*)d_in[3];   // [H,H]
    const float* b      = (const float*)d_in[4];   // [H]
    const float* W_out  = (const float*)d_in[5];   // [O,H]
    const float* b_out  = (const float*)d_in[6];   // [O]

    float* out    = (float*)d_out;                 // [B,T,O]
    float* hfinal = out + (size_t)BB * TT * OO;    // [B,H]

    xproj_kernel<<<dim3(512, 8), 256>>>(inputs, W_in);

    const size_t smem_bytes =
        (size_t)(JS * WSS + 2 * NB * HH + 8 * 256 + 8 * HH + JS) * sizeof(float);
    cudaFuncSetAttribute(rnn_scan_kernel, cudaFuncAttributeMaxDynamicSharedMemorySize,
                         (int)smem_bytes);

    cudaLaunchConfig_t cfg = {};
    cfg.gridDim = dim3((BB / NB) * CL);   // 16 clusters * 8 CTAs = 128 blocks
    cfg.blockDim = dim3(256);
    cfg.dynamicSmemBytes = smem_bytes;
    cudaLaunchAttribute attrs[1];
    attrs[0].id = cudaLaunchAttributeClusterDimension;
    attrs[0].val.clusterDim.x = CL;
    attrs[0].val.clusterDim.y = 1;
    attrs[0].val.clusterDim.z = 1;
    cfg.attrs = attrs;
    cfg.numAttrs = 1;

    cudaLaunchKernelEx(&cfg, rnn_scan_kernel, hidden, W_rec, b, W_out, b_out, out, hfinal);
}

// round 8
// speedup vs baseline: 1.5500x; 1.0326x over previous
#include <cuda_runtime.h>
#include <cuda_bf16.h>
#include <math.h>

// Problem constants (fixed shapes)
#define TT 512   // timesteps
#define BB 64    // batch
#define HH 512   // hidden
#define II 128   // input
#define OO 64    // output
#define CL 8     // CTAs per cluster
#define NB 4     // batches per cluster
#define JS 64    // hidden rows per CTA
#define ALPHA 0.1f

// Scratch (allowed: __device__ global)
__device__ float g_xproj[(size_t)BB * TT * HH];  // 64 MB

// ---------------- PTX helpers ----------------
__device__ __forceinline__ void fma2(unsigned long long& d,
                                     unsigned long long a,
                                     unsigned long long b) {
    asm("fma.rn.f32x2 %0, %1, %2, %0;" : "+l"(d) : "l"(a), "l"(b));
}
__device__ __forceinline__ float hadd2(unsigned long long v) {
    unsigned lo, hi;
    asm("mov.b64 {%0,%1}, %2;" : "=r"(lo), "=r"(hi) : "l"(v));
    return __uint_as_float(lo) + __uint_as_float(hi);
}
__device__ __forceinline__ unsigned long long pack2(float x, float y) {
    unsigned long long r;
    asm("mov.b64 %0, {%1, %2};" : "=l"(r) : "f"(x), "f"(y));
    return r;
}
__device__ __forceinline__ unsigned smem_u32(const void* p) {
    unsigned a;
    asm("{ .reg .u64 t; cvta.to.shared.u64 t, %1; cvt.u32.u64 %0, t; }"
        : "=r"(a) : "l"(p));
    return a;
}
__device__ __forceinline__ unsigned mapa_u32(unsigned addr, unsigned rank) {
    unsigned r;
    asm("mapa.shared::cluster.u32 %0, %1, %2;" : "=r"(r) : "r"(addr), "r"(rank));
    return r;
}
__device__ __forceinline__ void st_async64(unsigned addr, unsigned long long v,
                                           unsigned mbar) {
    asm volatile(
        "st.async.shared::cluster.mbarrier::complete_tx::bytes.b64 [%0], %1, [%2];"
        :: "r"(addr), "l"(v), "r"(mbar) : "memory");
}
__device__ __forceinline__ void mbar_init(unsigned addr, unsigned cnt) {
    asm volatile("mbarrier.init.shared.b64 [%0], %1;" :: "r"(addr), "r"(cnt) : "memory");
}
__device__ __forceinline__ void mbar_arrive(unsigned addr) {
    asm volatile("mbarrier.arrive.release.cluster.shared::cta.b64 _, [%0];"
                 :: "r"(addr) : "memory");
}
__device__ __forceinline__ void mbar_arrive_expect(unsigned addr, unsigned tx) {
    asm volatile("mbarrier.arrive.expect_tx.release.cluster.shared::cta.b64 _, [%0], %1;"
                 :: "r"(addr), "r"(tx) : "memory");
}
__device__ __forceinline__ void mbar_wait(unsigned addr, unsigned phase) {
    asm volatile(
        "{\n\t"
        ".reg .pred P;\n\t"
        "LW_%=:\n\t"
        "mbarrier.try_wait.parity.acquire.cluster.shared::cta.b64 P, [%0], %1, 0x989680;\n\t"
        "@P bra.uni LD_%=;\n\t"
        "bra.uni LW_%=;\n\t"
        "LD_%=:\n\t"
        "}"
        :: "r"(addr), "r"(phase) : "memory");
}
__device__ __forceinline__ float fast_tanh(float x) {
    float e = __expf(2.0f * x);
    return 1.0f - __fdividef(2.0f, e + 1.0f);
}

// ---------------------------------------------------------------------------
// Phase 1: x_proj[b,t,h] = sum_i inputs[b,t,i] * W_in[h,i]
// ---------------------------------------------------------------------------
__global__ void __launch_bounds__(256) xproj_kernel(const float* __restrict__ A,
                                                    const float* __restrict__ Win) {
    __shared__ float As[64 * 65];
    __shared__ float Bs[64 * 65];
    int mb = blockIdx.x;
    int hb = blockIdx.y;
    int tid = threadIdx.x;
    int tx = tid & 15, ty = tid >> 4;

    float acc[4][4];
#pragma unroll
    for (int i = 0; i < 4; ++i)
#pragma unroll
        for (int j = 0; j < 4; ++j) acc[i][j] = 0.f;

    for (int kc = 0; kc < 2; ++kc) {
#pragma unroll
        for (int i = 0; i < 4; ++i) {
            int f = tid + i * 256;
            int c4 = f & 15, r = f >> 4;
            float4 va = *(const float4*)(A + (size_t)(mb * 64 + r) * II + kc * 64 + c4 * 4);
            As[r * 65 + c4 * 4 + 0] = va.x;
            As[r * 65 + c4 * 4 + 1] = va.y;
            As[r * 65 + c4 * 4 + 2] = va.z;
            As[r * 65 + c4 * 4 + 3] = va.w;
            float4 vb = *(const float4*)(Win + (size_t)(hb * 64 + r) * II + kc * 64 + c4 * 4);
            Bs[r * 65 + c4 * 4 + 0] = vb.x;
            Bs[r * 65 + c4 * 4 + 1] = vb.y;
            Bs[r * 65 + c4 * 4 + 2] = vb.z;
            Bs[r * 65 + c4 * 4 + 3] = vb.w;
        }
        __syncthreads();
#pragma unroll 16
        for (int k = 0; k < 64; ++k) {
            float a0 = As[(ty * 4 + 0) * 65 + k];
            float a1 = As[(ty * 4 + 1) * 65 + k];
            float a2 = As[(ty * 4 + 2) * 65 + k];
            float a3 = As[(ty * 4 + 3) * 65 + k];
            float b0 = Bs[(tx * 4 + 0) * 65 + k];
            float b1 = Bs[(tx * 4 + 1) * 65 + k];
            float b2 = Bs[(tx * 4 + 2) * 65 + k];
            float b3 = Bs[(tx * 4 + 3) * 65 + k];
            acc[0][0] += a0 * b0; acc[0][1] += a0 * b1; acc[0][2] += a0 * b2; acc[0][3] += a0 * b3;
            acc[1][0] += a1 * b0; acc[1][1] += a1 * b1; acc[1][2] += a1 * b2; acc[1][3] += a1 * b3;
            acc[2][0] += a2 * b0; acc[2][1] += a2 * b1; acc[2][2] += a2 * b2; acc[2][3] += a2 * b3;
            acc[3][0] += a3 * b0; acc[3][1] += a3 * b1; acc[3][2] += a3 * b2; acc[3][3] += a3 * b3;
        }
        __syncthreads();
    }
#pragma unroll
    for (int i = 0; i < 4; ++i) {
        float4 v = make_float4(acc[i][0], acc[i][1], acc[i][2], acc[i][3]);
        *(float4*)(g_xproj + (size_t)(mb * 64 + ty * 4 + i) * HH + hb * 64 + tx * 4) = v;
    }
}

// ---------------------------------------------------------------------------
// SMEM layout (floats):
//   [0..4)        : 2 mbarriers (2 x u64)
//   [4..2052)     : hs0  [srcCTA(8)][batch(4)][64]
//   [2052..4100)  : hs1
//   [4100..6148)  : red  [warp(8)][256]
//   [6148..10244) : WoS  [8 rows][512]
//   [10244..10308): bsl  [64]
// ---------------------------------------------------------------------------
#define SM_HS0 4
#define SM_HS1 2052
#define SM_RED 4100
#define SM_WOS 6148
#define SM_BSL 10244
#define SM_TOT 10308

extern __shared__ float smem2[];

// deferred output: out[tOut] = W_out slice . h (h in [src][b][64] layout)
__device__ __forceinline__ void do_out(const float* __restrict__ h,
                                       const float* __restrict__ WoS,
                                       float* __restrict__ out,
                                       float4 bo4, int wb, int og,
                                       unsigned rank, int cbase, int lane, int tOut) {
    unsigned long long o0 = 0, o1 = 0, o2 = 0, o3 = 0;
#pragma unroll
    for (int m = 0; m < 4; ++m) {
        int hidx = ((lane >> 4) + 2 * m) * 256 + wb * 64 + (lane & 15) * 4;
        ulonglong2 hv = *(const ulonglong2*)&h[hidx];
        int kidx = lane * 4 + m * 128;
        ulonglong2 w0 = *(const ulonglong2*)&WoS[(og + 0) * HH + kidx];
        ulonglong2 w1 = *(const ulonglong2*)&WoS[(og + 1) * HH + kidx];
        ulonglong2 w2 = *(const ulonglong2*)&WoS[(og + 2) * HH + kidx];
        ulonglong2 w3 = *(const ulonglong2*)&WoS[(og + 3) * HH + kidx];
        fma2(o0, w0.x, hv.x); fma2(o0, w0.y, hv.y);
        fma2(o1, w1.x, hv.x); fma2(o1, w1.y, hv.y);
        fma2(o2, w2.x, hv.x); fma2(o2, w2.y, hv.y);
        fma2(o3, w3.x, hv.x); fma2(o3, w3.y, hv.y);
    }
    float f0 = hadd2(o0), f1 = hadd2(o1), f2 = hadd2(o2), f3 = hadd2(o3);
#pragma unroll
    for (int off = 16; off; off >>= 1) {
        f0 += __shfl_xor_sync(0xffffffffu, f0, off);
        f1 += __shfl_xor_sync(0xffffffffu, f1, off);
        f2 += __shfl_xor_sync(0xffffffffu, f2, off);
        f3 += __shfl_xor_sync(0xffffffffu, f3, off);
    }
    if (lane == 0) {
        float4 ov = make_float4(f0 + bo4.x, f1 + bo4.y, f2 + bo4.z, f3 + bo4.w);
        *(float4*)&out[((size_t)(cbase + wb) * TT + tOut) * OO + (int)rank * 8 + og] = ov;
    }
}

__global__ void __launch_bounds__(256, 1) rnn_scan_kernel(
    const float* __restrict__ hidden0,
    const float* __restrict__ Wrec,
    const float* __restrict__ bvec,
    const float* __restrict__ Wout,
    const float* __restrict__ bout,
    float* __restrict__ out,      // [B,T,O]
    float* __restrict__ hfinal)   // [B,H]
{
    float* hs0 = smem2 + SM_HS0;
    float* hs1 = smem2 + SM_HS1;
    float* red = smem2 + SM_RED;
    float* WoS = smem2 + SM_WOS;
    float* bsl = smem2 + SM_BSL;

    int tid = threadIdx.x;
    int lane = tid & 31, warp = tid >> 5;
    unsigned rank;
    asm("mov.u32 %0, %%cluster_ctarank;" : "=r"(rank));
    int cid = blockIdx.x / CL;
    int cbase = cid * NB;
    int jbase = (int)rank * JS;
    int rb = tid >> 6;             // batch (0..3)
    int jl = tid & 63;             // local hidden row
    int kb = warp * 64;            // this warp's k range

    // ---- W_rec slice into REGISTERS: rows (lane, lane+32), k in [kb, kb+64) ----
    unsigned long long w0r[32], w1r[32];
    {
        const float4* p0 = (const float4*)(Wrec + (size_t)(jbase + lane) * HH + kb);
        const float4* p1 = (const float4*)(Wrec + (size_t)(jbase + lane + 32) * HH + kb);
#pragma unroll
        for (int i = 0; i < 16; ++i) {
            float4 a = __ldg(p0 + i);
            float4 b = __ldg(p1 + i);
            w0r[2 * i]     = pack2(a.x, a.y);
            w0r[2 * i + 1] = pack2(a.z, a.w);
            w1r[2 * i]     = pack2(b.x, b.y);
            w1r[2 * i + 1] = pack2(b.z, b.w);
        }
    }

    // ---- W_out slice (8 rows) into SMEM ----
    for (int f = tid; f < 8 * HH / 4; f += 256) {
        int r = f >> 7, c4 = f & 127;
        *(float4*)&WoS[r * HH + c4 * 4] =
            *(const float4*)(Wout + (size_t)((int)rank * 8 + r) * HH + c4 * 4);
    }
    if (tid < JS) bsl[tid] = bvec[jbase + tid];

    int wb = warp >> 1;
    int og = (warp & 1) * 4;
    float4 bo4 = *(const float4*)(bout + (int)rank * 8 + og);

    // ---- initial hidden into hs0 ([src][b][64] layout) ----
    for (int f = tid; f < CL * NB * 64; f += 256) {
        int src = f >> 8, bb = (f >> 6) & 3, j = f & 63;
        hs0[f] = hidden0[(size_t)(cbase + bb) * HH + src * 64 + j];
    }

    // ---- mbarriers (count = 256 arrivals per phase) ----
    unsigned barb = smem_u32(smem2);   // hbar[0] at +0, hbar[1] at +8
    if (tid == 0) {
        mbar_init(barb, 256);
        mbar_init(barb + 8, 256);
    }
    __syncthreads();
    asm volatile("barrier.cluster.arrive.aligned;" ::: "memory");
    asm volatile("barrier.cluster.wait.aligned;" ::: "memory");

    // ---- precompute DSMEM scatter addressing (linear per-rank aperture) ----
    unsigned hs0_u = smem_u32(hs0);
    unsigned dst_off = (unsigned)(((int)rank * 256 + rb * 64 + jl) * 4);
    unsigned d0 = mapa_u32(hs0_u + dst_off, 0);
    unsigned stride = mapa_u32(hs0_u + dst_off, 1) - d0;
    unsigned b0 = mapa_u32(barb, 0);

    int ridx = ((jl >> 5) * 4 + rb) * 32 + (jl & 31);
    const float* cur = hs0;
    unsigned par0 = 0, par1 = 0;

    for (int t = 0; t < TT; ++t) {
        float xp = __ldg(&g_xproj[((size_t)(cbase + rb) * TT + t) * HH + jbase + jl]);

        // ---- recurrent GEMV slice: W in regs, h broadcast from SMEM ----
        const float* hb = cur + warp * 256;   // [4][64] for this warp's k range
        unsigned long long a00 = 0, a01 = 0, a02 = 0, a03 = 0;
        unsigned long long a10 = 0, a11 = 0, a12 = 0, a13 = 0;
#pragma unroll
        for (int m = 0; m < 16; ++m) {
            ulonglong2 h0 = *(const ulonglong2*)&hb[0 * 64 + m * 4];
            ulonglong2 h1 = *(const ulonglong2*)&hb[1 * 64 + m * 4];
            ulonglong2 h2 = *(const ulonglong2*)&hb[2 * 64 + m * 4];
            ulonglong2 h3 = *(const ulonglong2*)&hb[3 * 64 + m * 4];
            fma2(a00, w0r[2 * m], h0.x); fma2(a00, w0r[2 * m + 1], h0.y);
            fma2(a01, w0r[2 * m], h1.x); fma2(a01, w0r[2 * m + 1], h1.y);
            fma2(a02, w0r[2 * m], h2.x); fma2(a02, w0r[2 * m + 1], h2.y);
            fma2(a03, w0r[2 * m], h3.x); fma2(a03, w0r[2 * m + 1], h3.y);
            fma2(a10, w1r[2 * m], h0.x); fma2(a10, w1r[2 * m + 1], h0.y);
            fma2(a11, w1r[2 * m], h1.x); fma2(a11, w1r[2 * m + 1], h1.y);
            fma2(a12, w1r[2 * m], h2.x); fma2(a12, w1r[2 * m + 1], h2.y);
            fma2(a13, w1r[2 * m], h3.x); fma2(a13, w1r[2 * m + 1], h3.y);
        }
        red[warp * 256 + 0 * 32 + lane] = hadd2(a00);
        red[warp * 256 + 1 * 32 + lane] = hadd2(a01);
        red[warp * 256 + 2 * 32 + lane] = hadd2(a02);
        red[warp * 256 + 3 * 32 + lane] = hadd2(a03);
        red[warp * 256 + 4 * 32 + lane] = hadd2(a10);
        red[warp * 256 + 5 * 32 + lane] = hadd2(a11);
        red[warp * 256 + 6 * 32 + lane] = hadd2(a12);
        red[warp * 256 + 7 * 32 + lane] = hadd2(a13);

        // deferred output out_{t-1} = W_out . h_t (reads cur; off critical path)
        if (t > 0)
            do_out(cur, WoS, out, bo4, wb, og, rank, cbase, lane, t - 1);

        __syncthreads();

        float s = 0.f;
#pragma unroll
        for (int w = 0; w < 8; ++w) s += red[w * 256 + ridx];

        float pre = s + bsl[jl] + xp;
        float hp = cur[(int)rank * 256 + rb * 64 + jl];
        float hn = (1.0f - ALPHA) * hp + ALPHA * fast_tanh(pre);

        if (t == TT - 1) hfinal[(size_t)(cbase + rb) * HH + jbase + jl] = hn;

        // ---- scatter h_{t+1} to all 8 CTAs' next buffer via st.async ----
        float hpart = __shfl_xor_sync(0xffffffffu, hn, 1);
        unsigned idx = (unsigned)((t + 1) & 1);
        unsigned dbase = d0 + idx * (2048u * 4u);
        unsigned bbase = b0 + idx * 8u;
        if (!(jl & 1)) {
            unsigned long long val = pack2(hn, hpart);
#pragma unroll
            for (int r = 0; r < CL; ++r)
                st_async64(dbase + (unsigned)r * stride, val,
                           bbase + (unsigned)r * stride);
        }

        // arrive (count=256; tid0 also posts expected tx = 8KB)
        unsigned mybar = barb + idx * 8u;
        if (tid == 0) mbar_arrive_expect(mybar, 8192u);
        else          mbar_arrive(mybar);

        // wait for all arrivals + all 8KB of incoming h_{t+1}
        unsigned p = idx ? par1 : par0;
        mbar_wait(mybar, p);
        if (idx) par1 ^= 1; else par0 ^= 1;

        cur = idx ? hs1 : hs0;
    }

    // epilogue: out_{TT-1} from final hidden (cur = h_TT)
    do_out(cur, WoS, out, bo4, wb, og, rank, cbase, lane, TT - 1);
}

// ---------------------------------------------------------------------------
extern "C" void kernel_launch(void* const* d_in, const int* in_sizes, int n_in,
                              void* d_out, int out_size) {
    const float* inputs = (const float*)d_in[0];   // [B,T,I]
    const float* hidden = (const float*)d_in[1];   // [B,H]
    const float* W_in   = (const float*)d_in[2];   // [H,I]
    const float* W_rec  = (const float*)d_in[3];   // [H,H]
    const float* b      = (const float*)d_in[4];   // [H]
    const float* W_out  = (const float*)d_in[5];   // [O,H]
    const float* b_out  = (const float*)d_in[6];   // [O]

    float* out    = (float*)d_out;                 // [B,T,O]
    float* hfinal = out + (size_t)BB * TT * OO;    // [B,H]

    xproj_kernel<<<dim3(512, 8), 256>>>(inputs, W_in);

    const size_t smem_bytes = (size_t)SM_TOT * sizeof(float);
    cudaFuncSetAttribute(rnn_scan_kernel, cudaFuncAttributeMaxDynamicSharedMemorySize,
                         (int)smem_bytes);

    cudaLaunchConfig_t cfg = {};
    cfg.gridDim = dim3((BB / NB) * CL);   // 16 clusters * 8 CTAs = 128 blocks
    cfg.blockDim = dim3(256);
    cfg.dynamicSmemBytes = smem_bytes;
    cudaLaunchAttribute attrs[1];
    attrs[0].id = cudaLaunchAttributeClusterDimension;
    attrs[0].val.clusterDim.x = CL;
    attrs[0].val.clusterDim.y = 1;
    attrs[0].val.clusterDim.z = 1;
    cfg.attrs = attrs;
    cfg.numAttrs = 1;

    cudaLaunchKernelEx(&cfg, rnn_scan_kernel, hidden, W_rec, b, W_out, b_out, out, hfinal);
}